// round 1
// baseline (speedup 1.0000x reference)
#include <cuda_runtime.h>
#include <cuda_bf16.h>
#include <cstdint>

// Problem constants
#define VOCAB 32000
#define EMB   64
#define HID   64
#define BATCH 16
#define SEQ   256
#define ROWS  (BATCH*SEQ)   // 4096
#define G3    (3*HID)       // 192

// Scratch (device globals; no allocation allowed)
__device__ float g_xp[ROWS * G3];   // precomputed x @ w_ih^T + b_ih
__device__ float g_h [ROWS * HID];  // GRU hidden states

// ---------------------------------------------------------------------------
// Kernel 1: embedding lookup fused with input projection.
// grid = 256 blocks, block = 192 threads; each block handles 16 (b,s) rows.
// Thread g owns w_ih row g in registers; emb rows broadcast from smem.
// ---------------------------------------------------------------------------
__global__ __launch_bounds__(192) void embed_xp_kernel(
    const int* __restrict__ tokens, const float* __restrict__ emb,
    const float* __restrict__ w_ih, const float* __restrict__ b_ih)
{
    __shared__ __align__(16) float xs[16][EMB];
    __shared__ int toks[16];

    const int g = threadIdx.x;
    const int rowbase = blockIdx.x * 16;

    if (g < 16) toks[g] = tokens[rowbase + g];

    // w_ih row g -> registers (16 float4)
    float4 w4[16];
    const float4* wr = reinterpret_cast<const float4*>(w_ih + g * EMB);
#pragma unroll
    for (int i = 0; i < 16; ++i) w4[i] = wr[i];
    const float bi = b_ih[g];

    __syncthreads();
    // gather 16 embedding rows
    for (int idx = g; idx < 16 * EMB; idx += 192) {
        int r = idx >> 6, c = idx & 63;
        xs[r][c] = emb[(int64_t)toks[r] * EMB + c];
    }
    __syncthreads();

#pragma unroll 4
    for (int r = 0; r < 16; ++r) {
        const float4* xv = reinterpret_cast<const float4*>(xs[r]);
        float a0 = bi, a1 = 0.f, a2 = 0.f, a3 = 0.f;
#pragma unroll
        for (int i = 0; i < 16; ++i) {
            float4 h4 = xv[i];
            a0 += w4[i].x * h4.x;
            a1 += w4[i].y * h4.y;
            a2 += w4[i].z * h4.z;
            a3 += w4[i].w * h4.w;
        }
        g_xp[(rowbase + r) * G3 + g] = (a0 + a1) + (a2 + a3);
    }
}

// ---------------------------------------------------------------------------
// Kernel 2: GRU scan. 16 blocks (one per batch), 192 threads.
// Thread g owns w_hh row g in registers. h lives in smem, updated per step.
// hp[g<128] has xp fused in (r,z pre-activations); hp[g>=128] is hn only.
// ---------------------------------------------------------------------------
__device__ __forceinline__ float sigm(float x) { return 1.f / (1.f + expf(-x)); }

__global__ __launch_bounds__(192) void gru_scan_kernel(
    const float* __restrict__ w_hh, const float* __restrict__ b_hh)
{
    __shared__ __align__(16) float hsm[HID];
    __shared__ float hp[G3];

    const int g = threadIdx.x;
    const int b = blockIdx.x;

    float4 w4[16];
    const float4* wr = reinterpret_cast<const float4*>(w_hh + g * HID);
#pragma unroll
    for (int i = 0; i < 16; ++i) w4[i] = wr[i];
    const float bh = b_hh[g];

    if (g < HID) hsm[g] = 0.f;
    __syncthreads();

    for (int s = 0; s < SEQ; ++s) {
        const int row = b * SEQ + s;
        float base = bh;
        if (g < 2 * HID) base += g_xp[row * G3 + g];   // fuse xr/xz

        float a0 = base, a1 = 0.f, a2 = 0.f, a3 = 0.f;
        const float4* hv4 = reinterpret_cast<const float4*>(hsm);
#pragma unroll
        for (int i = 0; i < 16; ++i) {
            float4 h4 = hv4[i];
            a0 += w4[i].x * h4.x;
            a1 += w4[i].y * h4.y;
            a2 += w4[i].z * h4.z;
            a3 += w4[i].w * h4.w;
        }
        hp[g] = (a0 + a1) + (a2 + a3);
        __syncthreads();

        if (g < HID) {
            float r  = sigm(hp[g]);
            float z  = sigm(hp[HID + g]);
            float xn = g_xp[row * G3 + 2 * HID + g];
            float n  = tanhf(xn + r * hp[2 * HID + g]);
            float hnew = n + z * (hsm[g] - n);
            hsm[g] = hnew;
            g_h[row * HID + g] = hnew;
        }
        __syncthreads();
    }
}

// ---------------------------------------------------------------------------
// Kernel 3: output GEMM  C[4096,32000] = H[4096,64] @ W[32000,64]^T + bias
// tf32 mma.sync m16n8k8, block tile 64x128, K=64 staged once in smem.
// 256 threads = 8 warps (2x4), warp tile 32x32.
// ---------------------------------------------------------------------------
#define GM 64
#define GN 128
#define LDA 68
#define LDB 68
#define GEMM_SMEM_FLOATS (GM*LDA + GN*LDB + GN)
#define GEMM_SMEM_BYTES  (GEMM_SMEM_FLOATS * 4)

__device__ __forceinline__ float tf32r(float x) {
    unsigned u;
    asm("cvt.rna.tf32.f32 %0, %1;" : "=r"(u) : "f"(x));
    return __uint_as_float(u);
}

__device__ __forceinline__ void mma_tf32(float* d, const unsigned* a, const unsigned* b) {
    asm volatile(
        "mma.sync.aligned.m16n8k8.row.col.f32.tf32.tf32.f32 "
        "{%0,%1,%2,%3},{%4,%5,%6,%7},{%8,%9},{%0,%1,%2,%3};"
        : "+f"(d[0]), "+f"(d[1]), "+f"(d[2]), "+f"(d[3])
        : "r"(a[0]), "r"(a[1]), "r"(a[2]), "r"(a[3]), "r"(b[0]), "r"(b[1]));
}

__global__ __launch_bounds__(256) void out_gemm_kernel(
    const float* __restrict__ W, const float* __restrict__ bias,
    float* __restrict__ C)
{
    extern __shared__ float sm[];
    float* As  = sm;                 // [GM][LDA]
    float* Bs  = sm + GM * LDA;      // [GN][LDB]
    float* bss = Bs + GN * LDB;      // [GN]

    const int tid   = threadIdx.x;
    const int nbase = blockIdx.x * GN;
    const int mbase = blockIdx.y * GM;

    // stage A (H rows mbase..mbase+63), converting to tf32
    const float4* Hg = reinterpret_cast<const float4*>(g_h + mbase * HID);
#pragma unroll
    for (int i = 0; i < 4; ++i) {
        int idx = tid + i * 256;           // 0..1023 float4s
        float4 v = Hg[idx];
        int m = idx >> 4, k = (idx & 15) << 2;
        float* dst = As + m * LDA + k;
        dst[0] = tf32r(v.x); dst[1] = tf32r(v.y);
        dst[2] = tf32r(v.z); dst[3] = tf32r(v.w);
    }
    // stage B (w_out rows nbase..nbase+127)
    const float4* Wg = reinterpret_cast<const float4*>(W + (size_t)nbase * HID);
#pragma unroll
    for (int i = 0; i < 8; ++i) {
        int idx = tid + i * 256;           // 0..2047 float4s
        float4 v = Wg[idx];
        int n = idx >> 4, k = (idx & 15) << 2;
        float* dst = Bs + n * LDB + k;
        dst[0] = tf32r(v.x); dst[1] = tf32r(v.y);
        dst[2] = tf32r(v.z); dst[3] = tf32r(v.w);
    }
    if (tid < GN) bss[tid] = bias[nbase + tid];
    __syncthreads();

    const int w    = tid >> 5;
    const int lane = tid & 31;
    const int wm   = w >> 2;       // 0..1  (M)
    const int wn   = w & 3;        // 0..3  (N)
    const int gid  = lane >> 2;    // 0..7
    const int tg   = lane & 3;     // 0..3

    float acc[2][4][4];
#pragma unroll
    for (int mf = 0; mf < 2; ++mf)
#pragma unroll
        for (int nf = 0; nf < 4; ++nf)
#pragma unroll
            for (int r = 0; r < 4; ++r) acc[mf][nf][r] = 0.f;

#pragma unroll
    for (int k8 = 0; k8 < 8; ++k8) {
        const int kb = k8 * 8;
        unsigned a[2][4];
#pragma unroll
        for (int mf = 0; mf < 2; ++mf) {
            int m = wm * 32 + mf * 16 + gid;
            const float* ap = As + m * LDA + kb + tg;
            a[mf][0] = __float_as_uint(ap[0]);
            a[mf][1] = __float_as_uint(ap[8 * LDA]);
            a[mf][2] = __float_as_uint(ap[4]);
            a[mf][3] = __float_as_uint(ap[8 * LDA + 4]);
        }
#pragma unroll
        for (int nf = 0; nf < 4; ++nf) {
            int n = wn * 32 + nf * 8 + gid;
            const float* bp = Bs + n * LDB + kb + tg;
            unsigned bfr[2];
            bfr[0] = __float_as_uint(bp[0]);
            bfr[1] = __float_as_uint(bp[4]);
#pragma unroll
            for (int mf = 0; mf < 2; ++mf)
                mma_tf32(acc[mf][nf], a[mf], bfr);
        }
    }

    // epilogue: bias add + float2 stores
#pragma unroll
    for (int mf = 0; mf < 2; ++mf) {
        const int row0 = mbase + wm * 32 + mf * 16 + gid;
#pragma unroll
        for (int nf = 0; nf < 4; ++nf) {
            const int c   = wn * 32 + nf * 8 + 2 * tg;
            const int col = nbase + c;
            const float b0 = bss[c], b1 = bss[c + 1];
            float2 v0 = make_float2(acc[mf][nf][0] + b0, acc[mf][nf][1] + b1);
            float2 v1 = make_float2(acc[mf][nf][2] + b0, acc[mf][nf][3] + b1);
            *reinterpret_cast<float2*>(C + (size_t)row0 * VOCAB + col)       = v0;
            *reinterpret_cast<float2*>(C + (size_t)(row0 + 8) * VOCAB + col) = v1;
        }
    }
}

// ---------------------------------------------------------------------------
// Launch
// Inputs: 0 tokens(int32) 1 emb 2 w_ih 3 w_hh 4 b_ih 5 b_hh 6 w_out 7 b_out
// ---------------------------------------------------------------------------
extern "C" void kernel_launch(void* const* d_in, const int* in_sizes, int n_in,
                              void* d_out, int out_size)
{
    const int*   tokens = (const int*)  d_in[0];
    const float* emb    = (const float*)d_in[1];
    const float* w_ih   = (const float*)d_in[2];
    const float* w_hh   = (const float*)d_in[3];
    const float* b_ih   = (const float*)d_in[4];
    const float* b_hh   = (const float*)d_in[5];
    const float* w_out  = (const float*)d_in[6];
    const float* b_out  = (const float*)d_in[7];
    float* out = (float*)d_out;

    (void)in_sizes; (void)n_in; (void)out_size;

    cudaFuncSetAttribute(out_gemm_kernel,
                         cudaFuncAttributeMaxDynamicSharedMemorySize,
                         GEMM_SMEM_BYTES);

    embed_xp_kernel<<<ROWS / 16, 192>>>(tokens, emb, w_ih, b_ih);
    gru_scan_kernel<<<BATCH, 192>>>(w_hh, b_hh);

    dim3 grid(VOCAB / GN, ROWS / GM);   // 250 x 64
    out_gemm_kernel<<<grid, 256, GEMM_SMEM_BYTES>>>(w_out, b_out, out);
}

// round 3
// speedup vs baseline: 1.5783x; 1.5783x over previous
#include <cuda_runtime.h>
#include <cuda_fp16.h>
#include <cstdint>

// Problem constants
#define VOCAB 32000
#define EMB   64
#define HID   64
#define BATCH 16
#define SEQ   256
#define ROWS  (BATCH*SEQ)   // 4096
#define G3    (3*HID)       // 192

// Scratch (device globals; no allocation allowed)
__device__ float  g_xp[ROWS * G3];          // x @ w_ih^T + b_ih
__device__ __half g_hh[ROWS * HID];         // GRU hidden states (fp16)
__device__ __half g_wh[VOCAB * HID];        // w_out converted to fp16

// ---------------------------------------------------------------------------
// Kernel 0: convert w_out fp32 -> fp16
// ---------------------------------------------------------------------------
__global__ __launch_bounds__(256) void wconv_kernel(const float* __restrict__ W)
{
    size_t i = (size_t)blockIdx.x * blockDim.x + threadIdx.x;  // over 512000 float4
    float4 v = reinterpret_cast<const float4*>(W)[i];
    __half2* d = reinterpret_cast<__half2*>(g_wh + i * 4);
    d[0] = __floats2half2_rn(v.x, v.y);
    d[1] = __floats2half2_rn(v.z, v.w);
}

// ---------------------------------------------------------------------------
// Kernel 1: embedding lookup fused with input projection.
// 128 blocks x 192 threads; 32 (b,s) rows per block.
// ---------------------------------------------------------------------------
__global__ __launch_bounds__(192) void embed_xp_kernel(
    const int* __restrict__ tokens, const float* __restrict__ emb,
    const float* __restrict__ w_ih, const float* __restrict__ b_ih)
{
    __shared__ __align__(16) float xs[32][EMB];
    __shared__ int toks[32];

    const int g = threadIdx.x;
    const int rowbase = blockIdx.x * 32;

    if (g < 32) toks[g] = tokens[rowbase + g];

    float4 w4[16];
    const float4* wr = reinterpret_cast<const float4*>(w_ih + g * EMB);
#pragma unroll
    for (int i = 0; i < 16; ++i) w4[i] = wr[i];
    const float bi = b_ih[g];

    __syncthreads();
    for (int idx = g; idx < 32 * EMB; idx += 192) {
        int r = idx >> 6, c = idx & 63;
        xs[r][c] = emb[(int64_t)toks[r] * EMB + c];
    }
    __syncthreads();

#pragma unroll 4
    for (int r = 0; r < 32; ++r) {
        const float4* xv = reinterpret_cast<const float4*>(xs[r]);
        float a0 = bi, a1 = 0.f, a2 = 0.f, a3 = 0.f;
#pragma unroll
        for (int i = 0; i < 16; ++i) {
            float4 h4 = xv[i];
            a0 += w4[i].x * h4.x;
            a1 += w4[i].y * h4.y;
            a2 += w4[i].z * h4.z;
            a3 += w4[i].w * h4.w;
        }
        g_xp[(rowbase + r) * G3 + g] = (a0 + a1) + (a2 + a3);
    }
}

// ---------------------------------------------------------------------------
// Kernel 2: GRU scan. 16 blocks (one per batch), 192 threads.
// Prefetches next step's xp/xn during the current step to hide LDG latency.
// ---------------------------------------------------------------------------
__device__ __forceinline__ float sigm(float x) { return 1.f / (1.f + expf(-x)); }

__global__ __launch_bounds__(192) void gru_scan_kernel(
    const float* __restrict__ w_hh, const float* __restrict__ b_hh)
{
    __shared__ __align__(16) float hsm[HID];
    __shared__ float hp[G3];

    const int g = threadIdx.x;
    const int b = blockIdx.x;
    const int row0 = b * SEQ;

    float4 w4[16];
    const float4* wr = reinterpret_cast<const float4*>(w_hh + g * HID);
#pragma unroll
    for (int i = 0; i < 16; ++i) w4[i] = wr[i];
    const float bh = b_hh[g];

    if (g < HID) hsm[g] = 0.f;

    // preload step 0 inputs
    float xp_c = (g < 2 * HID) ? g_xp[(size_t)row0 * G3 + g] : 0.f;
    float xn_c = (g < HID)     ? g_xp[(size_t)row0 * G3 + 2 * HID + g] : 0.f;
    __syncthreads();

    for (int s = 0; s < SEQ; ++s) {
        const int row = row0 + s;
        // prefetch next step
        float xp_n = 0.f, xn_n = 0.f;
        if (s + 1 < SEQ) {
            if (g < 2 * HID) xp_n = g_xp[(size_t)(row + 1) * G3 + g];
            if (g < HID)     xn_n = g_xp[(size_t)(row + 1) * G3 + 2 * HID + g];
        }

        float a0 = bh + xp_c, a1 = 0.f, a2 = 0.f, a3 = 0.f;
        const float4* hv4 = reinterpret_cast<const float4*>(hsm);
#pragma unroll
        for (int i = 0; i < 16; ++i) {
            float4 h4 = hv4[i];
            a0 += w4[i].x * h4.x;
            a1 += w4[i].y * h4.y;
            a2 += w4[i].z * h4.z;
            a3 += w4[i].w * h4.w;
        }
        hp[g] = (a0 + a1) + (a2 + a3);
        __syncthreads();

        if (g < HID) {
            float r  = sigm(hp[g]);
            float z  = sigm(hp[HID + g]);
            float n  = tanhf(xn_c + r * hp[2 * HID + g]);
            float hnew = n + z * (hsm[g] - n);
            hsm[g] = hnew;
            g_hh[(size_t)row * HID + g] = __float2half_rn(hnew);
        }
        __syncthreads();

        xp_c = xp_n; xn_c = xn_n;
    }
}

// ---------------------------------------------------------------------------
// Kernel 3: output GEMM  C[4096,32000] = H[4096,64] @ W[32000,64]^T + bias
// fp16 mma.sync m16n8k16, f32 accum. Block 128x128, 8 warps of 64x32.
// K=64 staged once in SMEM (pad-72 rows), fragments via ldmatrix.x4.
// ---------------------------------------------------------------------------
#define GM 128
#define GN 128
#define LDS_H 72   // halves per smem row (64 + 8 pad => 16B-aligned, conflict-free)

__device__ __forceinline__ void ldsm_x4(uint32_t* r, uint32_t addr) {
    asm volatile("ldmatrix.sync.aligned.m8n8.x4.shared.b16 {%0,%1,%2,%3}, [%4];"
                 : "=r"(r[0]), "=r"(r[1]), "=r"(r[2]), "=r"(r[3]) : "r"(addr));
}
__device__ __forceinline__ void mma16816(float* d, const uint32_t* a, const uint32_t* b) {
    asm volatile(
        "mma.sync.aligned.m16n8k16.row.col.f32.f16.f16.f32 "
        "{%0,%1,%2,%3},{%4,%5,%6,%7},{%8,%9},{%0,%1,%2,%3};"
        : "+f"(d[0]), "+f"(d[1]), "+f"(d[2]), "+f"(d[3])
        : "r"(a[0]), "r"(a[1]), "r"(a[2]), "r"(a[3]), "r"(b[0]), "r"(b[1]));
}
__device__ __forceinline__ uint32_t smem_u32(const void* p) {
    uint32_t a;
    asm("{ .reg .u64 t; cvta.to.shared.u64 t, %1; cvt.u32.u64 %0, t; }"
        : "=r"(a) : "l"(p));
    return a;
}

__global__ __launch_bounds__(256, 2) void out_gemm_kernel(
    const float* __restrict__ bias, float* __restrict__ C)
{
    __shared__ __align__(16) __half As[GM * LDS_H];
    __shared__ __align__(16) __half Bs[GN * LDS_H];

    const int tid   = threadIdx.x;
    const int wid   = tid >> 5;
    const int lane  = tid & 31;
    const int wm    = wid >> 2;     // 0..1  (M: 64 rows each)
    const int wn    = wid & 3;      // 0..3  (N: 32 cols each)
    const int nbase = blockIdx.x * GN;
    const int mbase = blockIdx.y * GM;

    // ---- stage A (g_hh rows mbase..+127) and B (g_wh rows nbase..+127) ----
    {
        const uint4* Ag = reinterpret_cast<const uint4*>(g_hh + (size_t)mbase * HID);
        const uint4* Bg = reinterpret_cast<const uint4*>(g_wh + (size_t)nbase * HID);
#pragma unroll
        for (int i = 0; i < 4; ++i) {
            int idx = tid + i * 256;           // 0..1023 uint4 (8 halves each)
            int m = idx >> 3, c = idx & 7;
            *reinterpret_cast<uint4*>(As + m * LDS_H + c * 8) = Ag[idx];
            *reinterpret_cast<uint4*>(Bs + m * LDS_H + c * 8) = Bg[idx];
        }
    }
    __syncthreads();

    const uint32_t As_u = smem_u32(As);
    const uint32_t Bs_u = smem_u32(Bs);

    // ldmatrix lane addressing (byte offsets; row stride = 144B, k-chunk = 16B)
    const int a_row = wm * 64 + ((lane >> 3) & 1) * 8 + (lane & 7);
    const int a_kc  = (lane >> 4) * 16;
    const int b_row = wn * 32 + (lane >> 4) * 8 + (lane & 7);
    const int b_kc  = ((lane >> 3) & 1) * 16;

    float acc[4][4][4];
#pragma unroll
    for (int mt = 0; mt < 4; ++mt)
#pragma unroll
        for (int nt = 0; nt < 4; ++nt)
#pragma unroll
            for (int r = 0; r < 4; ++r) acc[mt][nt][r] = 0.f;

#pragma unroll
    for (int ks = 0; ks < 4; ++ks) {
        uint32_t a[4][4], bfr[2][4];
#pragma unroll
        for (int mt = 0; mt < 4; ++mt)
            ldsm_x4(a[mt], As_u + (uint32_t)((a_row + mt * 16) * 144 + ks * 32 + a_kc));
#pragma unroll
        for (int p = 0; p < 2; ++p)
            ldsm_x4(bfr[p], Bs_u + (uint32_t)((b_row + p * 16) * 144 + ks * 32 + b_kc));
#pragma unroll
        for (int mt = 0; mt < 4; ++mt)
#pragma unroll
            for (int nt = 0; nt < 4; ++nt)
                mma16816(acc[mt][nt], a[mt], &bfr[nt >> 1][(nt & 1) * 2]);
    }

    // ---- epilogue: bias add + direct float2 stores ----
    const int row_l = mbase + wm * 64 + (lane >> 2);
    const int col_l = nbase + wn * 32 + 2 * (lane & 3);
    float2 bv[4];
#pragma unroll
    for (int nt = 0; nt < 4; ++nt)
        bv[nt] = *reinterpret_cast<const float2*>(bias + col_l + nt * 8);

#pragma unroll
    for (int mt = 0; mt < 4; ++mt) {
        const size_t r0 = (size_t)(row_l + mt * 16) * VOCAB;
        const size_t r1 = (size_t)(row_l + mt * 16 + 8) * VOCAB;
#pragma unroll
        for (int nt = 0; nt < 4; ++nt) {
            float2 v0 = make_float2(acc[mt][nt][0] + bv[nt].x, acc[mt][nt][1] + bv[nt].y);
            float2 v1 = make_float2(acc[mt][nt][2] + bv[nt].x, acc[mt][nt][3] + bv[nt].y);
            *reinterpret_cast<float2*>(C + r0 + col_l + nt * 8) = v0;
            *reinterpret_cast<float2*>(C + r1 + col_l + nt * 8) = v1;
        }
    }
}

// ---------------------------------------------------------------------------
// Launch
// Inputs: 0 tokens(int32) 1 emb 2 w_ih 3 w_hh 4 b_ih 5 b_hh 6 w_out 7 b_out
// ---------------------------------------------------------------------------
extern "C" void kernel_launch(void* const* d_in, const int* in_sizes, int n_in,
                              void* d_out, int out_size)
{
    const int*   tokens = (const int*)  d_in[0];
    const float* emb    = (const float*)d_in[1];
    const float* w_ih   = (const float*)d_in[2];
    const float* w_hh   = (const float*)d_in[3];
    const float* b_ih   = (const float*)d_in[4];
    const float* b_hh   = (const float*)d_in[5];
    const float* w_out  = (const float*)d_in[6];
    const float* b_out  = (const float*)d_in[7];
    float* out = (float*)d_out;

    (void)in_sizes; (void)n_in; (void)out_size;

    wconv_kernel<<<VOCAB * HID / 4 / 256, 256>>>(w_out);
    embed_xp_kernel<<<ROWS / 32, 192>>>(tokens, emb, w_ih, b_ih);
    gru_scan_kernel<<<BATCH, 192>>>(w_hh, b_hh);

    dim3 grid(VOCAB / GN, ROWS / GM);   // 250 x 32
    out_gemm_kernel<<<grid, 256>>>(b_out, out);
}

// round 4
// speedup vs baseline: 1.6665x; 1.0559x over previous
#include <cuda_runtime.h>
#include <cuda_fp16.h>
#include <cstdint>

// Problem constants
#define VOCAB 32000
#define EMB   64
#define HID   64
#define BATCH 16
#define SEQ   256
#define ROWS  (BATCH*SEQ)   // 4096
#define G3    (3*HID)       // 192

// Scratch (device globals; no allocation allowed)
__device__ float  g_xp[ROWS * G3];          // x @ w_ih^T + b_ih
__device__ __half g_hh[ROWS * HID];         // GRU hidden states (fp16)
__device__ __half g_wh[VOCAB * HID];        // w_out converted to fp16

// ---------------------------------------------------------------------------
// packed f32x2 helpers (sm_103a)
// ---------------------------------------------------------------------------
__device__ __forceinline__ void fma2(unsigned long long& d,
                                     unsigned long long a, unsigned long long b) {
    asm("fma.rn.f32x2 %0, %1, %2, %0;" : "+l"(d) : "l"(a), "l"(b));
}
__device__ __forceinline__ float upsum(unsigned long long v) {
    unsigned lo, hi;
    asm("mov.b64 {%0,%1}, %2;" : "=r"(lo), "=r"(hi) : "l"(v));
    return __uint_as_float(lo) + __uint_as_float(hi);
}
__device__ __forceinline__ float frcp(float x) {
    float r; asm("rcp.approx.f32 %0, %1;" : "=f"(r) : "f"(x)); return r;
}
__device__ __forceinline__ float fsigm(float x) {
    return frcp(1.f + __expf(-x));
}
__device__ __forceinline__ float ftanh(float x) {
    return 1.f - 2.f * frcp(__expf(2.f * x) + 1.f);
}

// ---------------------------------------------------------------------------
// Kernel 0: convert w_out fp32 -> fp16
// ---------------------------------------------------------------------------
__global__ __launch_bounds__(256) void wconv_kernel(const float* __restrict__ W)
{
    size_t i = (size_t)blockIdx.x * blockDim.x + threadIdx.x;  // over 512000 float4
    float4 v = reinterpret_cast<const float4*>(W)[i];
    __half2* d = reinterpret_cast<__half2*>(g_wh + i * 4);
    d[0] = __floats2half2_rn(v.x, v.y);
    d[1] = __floats2half2_rn(v.z, v.w);
}

// ---------------------------------------------------------------------------
// Kernel 1: embedding lookup fused with input projection.
// 128 blocks x 192 threads; 32 (b,s) rows per block.
// ---------------------------------------------------------------------------
__global__ __launch_bounds__(192) void embed_xp_kernel(
    const int* __restrict__ tokens, const float* __restrict__ emb,
    const float* __restrict__ w_ih, const float* __restrict__ b_ih)
{
    __shared__ __align__(16) float xs[32][EMB];
    __shared__ int toks[32];

    const int g = threadIdx.x;
    const int rowbase = blockIdx.x * 32;

    if (g < 32) toks[g] = tokens[rowbase + g];

    float4 w4[16];
    const float4* wr = reinterpret_cast<const float4*>(w_ih + g * EMB);
#pragma unroll
    for (int i = 0; i < 16; ++i) w4[i] = wr[i];
    const float bi = b_ih[g];

    __syncthreads();
    for (int idx = g; idx < 32 * EMB; idx += 192) {
        int r = idx >> 6, c = idx & 63;
        xs[r][c] = emb[(int64_t)toks[r] * EMB + c];
    }
    __syncthreads();

#pragma unroll 4
    for (int r = 0; r < 32; ++r) {
        const float4* xv = reinterpret_cast<const float4*>(xs[r]);
        float a0 = bi, a1 = 0.f, a2 = 0.f, a3 = 0.f;
#pragma unroll
        for (int i = 0; i < 16; ++i) {
            float4 h4 = xv[i];
            a0 += w4[i].x * h4.x;
            a1 += w4[i].y * h4.y;
            a2 += w4[i].z * h4.z;
            a3 += w4[i].w * h4.w;
        }
        g_xp[(rowbase + r) * G3 + g] = (a0 + a1) + (a2 + a3);
    }
}

// ---------------------------------------------------------------------------
// Kernel 2: GRU scan. 16 blocks (one per batch), 128 threads (4 warps).
// Thread pair (g = t>>1, half = t&1): each thread computes all 3 gate dots
// for h-index g over a 32-wide k-half using packed f32x2 FMAs, merges halves
// with one shfl per gate, computes activations redundantly. Ping-pong h
// buffer -> single __syncthreads per step. xp prefetched one step ahead.
// ---------------------------------------------------------------------------
__global__ __launch_bounds__(128) void gru_scan_kernel(
    const float* __restrict__ w_hh, const float* __restrict__ b_hh)
{
    __shared__ __align__(16) float hsm[2][HID];

    const int t    = threadIdx.x;
    const int p    = t >> 1;        // h index 0..63
    const int half = t & 1;         // k half
    const int k0   = half * 32;
    const int row0 = blockIdx.x * SEQ;

    // weights: rows p, p+64, p+128, k-slice [k0, k0+32) as 16 packed u64 each
    unsigned long long wr[16], wz[16], wn[16];
    {
        const unsigned long long* Wr =
            reinterpret_cast<const unsigned long long*>(w_hh + (p      ) * HID + k0);
        const unsigned long long* Wz =
            reinterpret_cast<const unsigned long long*>(w_hh + (p +  64) * HID + k0);
        const unsigned long long* Wn =
            reinterpret_cast<const unsigned long long*>(w_hh + (p + 128) * HID + k0);
#pragma unroll
        for (int i = 0; i < 16; ++i) { wr[i] = Wr[i]; wz[i] = Wz[i]; wn[i] = Wn[i]; }
    }
    const float br = b_hh[p], bz = b_hh[p + 64], bn = b_hh[p + 128];

    if (t < HID) { hsm[0][t] = 0.f; hsm[1][t] = 0.f; }

    // prefetch step 0 xp
    const float* xp0 = g_xp + (size_t)row0 * G3;
    float xr = xp0[p], xz = xp0[p + 64], xn = xp0[p + 128];
    float h_old = 0.f;
    __syncthreads();

    int cur = 0;
#pragma unroll 1
    for (int s = 0; s < SEQ; ++s) {
        // prefetch next step's xp
        float xr_n = 0.f, xz_n = 0.f, xn_n = 0.f;
        if (s + 1 < SEQ) {
            const float* xpn = g_xp + (size_t)(row0 + s + 1) * G3;
            xr_n = xpn[p]; xz_n = xpn[p + 64]; xn_n = xpn[p + 128];
        }

        // 3-gate partial matvec over k-half (packed f32x2)
        unsigned long long ar0 = 0, ar1 = 0, az0 = 0, az1 = 0, an0 = 0, an1 = 0;
        const unsigned long long* h2 =
            reinterpret_cast<const unsigned long long*>(&hsm[cur][k0]);
#pragma unroll
        for (int i = 0; i < 16; i += 2) {
            unsigned long long h0 = h2[i], h1 = h2[i + 1];
            fma2(ar0, wr[i], h0); fma2(ar1, wr[i + 1], h1);
            fma2(az0, wz[i], h0); fma2(az1, wz[i + 1], h1);
            fma2(an0, wn[i], h0); fma2(an1, wn[i + 1], h1);
        }
        float dr = upsum(ar0) + upsum(ar1);
        float dz = upsum(az0) + upsum(az1);
        float dn = upsum(an0) + upsum(an1);
        dr += __shfl_xor_sync(0xffffffffu, dr, 1);
        dz += __shfl_xor_sync(0xffffffffu, dz, 1);
        dn += __shfl_xor_sync(0xffffffffu, dn, 1);

        const float r = fsigm(xr + br + dr);
        const float z = fsigm(xz + bz + dz);
        const float n = ftanh(xn + r * (dn + bn));
        const float hnew = n + z * (h_old - n);

        if (!half) {
            hsm[cur ^ 1][p] = hnew;
            g_hh[(size_t)(row0 + s) * HID + p] = __float2half_rn(hnew);
        }
        h_old = hnew;
        __syncthreads();
        cur ^= 1;
        xr = xr_n; xz = xz_n; xn = xn_n;
    }
}

// ---------------------------------------------------------------------------
// Kernel 3: output GEMM  C[4096,32000] = H[4096,64] @ W[32000,64]^T + bias
// fp16 mma.sync m16n8k16, f32 accum. Block 128x128, 8 warps of 64x32.
// K=64 staged once in SMEM (pad-72 rows), fragments via ldmatrix.x4.
// Epilogue: stage C tile through SMEM (reusing dead A/B tiles) ->
// coalesced float4 row stores.
// ---------------------------------------------------------------------------
#define GM 128
#define GN 128
#define LDS_H 72          // halves per smem row (64 + 8 pad)
#define STG_PITCH 132     // floats per stage row (128 + 4 pad)

__device__ __forceinline__ void ldsm_x4(uint32_t* r, uint32_t addr) {
    asm volatile("ldmatrix.sync.aligned.m8n8.x4.shared.b16 {%0,%1,%2,%3}, [%4];"
                 : "=r"(r[0]), "=r"(r[1]), "=r"(r[2]), "=r"(r[3]) : "r"(addr));
}
__device__ __forceinline__ void mma16816(float* d, const uint32_t* a, const uint32_t* b) {
    asm volatile(
        "mma.sync.aligned.m16n8k16.row.col.f32.f16.f16.f32 "
        "{%0,%1,%2,%3},{%4,%5,%6,%7},{%8,%9},{%0,%1,%2,%3};"
        : "+f"(d[0]), "+f"(d[1]), "+f"(d[2]), "+f"(d[3])
        : "r"(a[0]), "r"(a[1]), "r"(a[2]), "r"(a[3]), "r"(b[0]), "r"(b[1]));
}
__device__ __forceinline__ uint32_t smem_u32(const void* p) {
    uint32_t a;
    asm("{ .reg .u64 t; cvta.to.shared.u64 t, %1; cvt.u32.u64 %0, t; }"
        : "=r"(a) : "l"(p));
    return a;
}

__global__ __launch_bounds__(256, 2) void out_gemm_kernel(
    const float* __restrict__ bias, float* __restrict__ C)
{
    __shared__ __align__(16) char smraw[GM * LDS_H * 2 + GN * LDS_H * 2];  // 36864 B
    __half* As = reinterpret_cast<__half*>(smraw);
    __half* Bs = As + GM * LDS_H;
    float* stage = reinterpret_cast<float*>(smraw);   // 64*132*4 = 33792 B overlay

    const int tid   = threadIdx.x;
    const int wid   = tid >> 5;
    const int lane  = tid & 31;
    const int wm    = wid >> 2;     // 0..1  (M: 64 rows each)
    const int wn    = wid & 3;      // 0..3  (N: 32 cols each)
    const int nbase = blockIdx.x * GN;
    const int mbase = blockIdx.y * GM;

    // ---- stage A (g_hh rows mbase..+127) and B (g_wh rows nbase..+127) ----
    {
        const uint4* Ag = reinterpret_cast<const uint4*>(g_hh + (size_t)mbase * HID);
        const uint4* Bg = reinterpret_cast<const uint4*>(g_wh + (size_t)nbase * HID);
#pragma unroll
        for (int i = 0; i < 4; ++i) {
            int idx = tid + i * 256;           // 0..1023 uint4 (8 halves each)
            int m = idx >> 3, c = idx & 7;
            *reinterpret_cast<uint4*>(As + m * LDS_H + c * 8) = Ag[idx];
            *reinterpret_cast<uint4*>(Bs + m * LDS_H + c * 8) = Bg[idx];
        }
    }
    __syncthreads();

    const uint32_t As_u = smem_u32(As);
    const uint32_t Bs_u = smem_u32(Bs);

    const int a_row = wm * 64 + ((lane >> 3) & 1) * 8 + (lane & 7);
    const int a_kc  = (lane >> 4) * 16;
    const int b_row = wn * 32 + (lane >> 4) * 8 + (lane & 7);
    const int b_kc  = ((lane >> 3) & 1) * 16;

    float acc[4][4][4];
#pragma unroll
    for (int mt = 0; mt < 4; ++mt)
#pragma unroll
        for (int nt = 0; nt < 4; ++nt)
#pragma unroll
            for (int r = 0; r < 4; ++r) acc[mt][nt][r] = 0.f;

#pragma unroll
    for (int ks = 0; ks < 4; ++ks) {
        uint32_t a[4][4], bfr[2][4];
#pragma unroll
        for (int mt = 0; mt < 4; ++mt)
            ldsm_x4(a[mt], As_u + (uint32_t)((a_row + mt * 16) * 144 + ks * 32 + a_kc));
#pragma unroll
        for (int p = 0; p < 2; ++p)
            ldsm_x4(bfr[p], Bs_u + (uint32_t)((b_row + p * 16) * 144 + ks * 32 + b_kc));
#pragma unroll
        for (int mt = 0; mt < 4; ++mt)
#pragma unroll
            for (int nt = 0; nt < 4; ++nt)
                mma16816(acc[mt][nt], a[mt], &bfr[nt >> 1][(nt & 1) * 2]);
    }

    // ---- epilogue: bias add, SMEM stage (reuse A/B), coalesced stores ----
    const int col_l = wn * 32 + 2 * (lane & 3);
    float2 bv[4];
#pragma unroll
    for (int nt = 0; nt < 4; ++nt)
        bv[nt] = *reinterpret_cast<const float2*>(bias + nbase + col_l + nt * 8);

    __syncthreads();   // A/B smem dead -> stage overlay safe

#pragma unroll 1
    for (int pass = 0; pass < 2; ++pass) {
        if (wm == pass) {
#pragma unroll
            for (int mt = 0; mt < 4; ++mt) {
                const int r0 = mt * 16 + (lane >> 2);
#pragma unroll
                for (int nt = 0; nt < 4; ++nt) {
                    const int c = col_l + nt * 8;
                    float2 v0 = make_float2(acc[mt][nt][0] + bv[nt].x,
                                            acc[mt][nt][1] + bv[nt].y);
                    float2 v1 = make_float2(acc[mt][nt][2] + bv[nt].x,
                                            acc[mt][nt][3] + bv[nt].y);
                    *reinterpret_cast<float2*>(stage + r0 * STG_PITCH + c)       = v0;
                    *reinterpret_cast<float2*>(stage + (r0 + 8) * STG_PITCH + c) = v1;
                }
            }
        }
        __syncthreads();
#pragma unroll
        for (int i = 0; i < 8; ++i) {
            int idx = tid + i * 256;            // 0..2047
            int r = idx >> 5, c4 = (idx & 31) << 2;
            float4 v = *reinterpret_cast<const float4*>(stage + r * STG_PITCH + c4);
            *reinterpret_cast<float4*>(
                C + (size_t)(mbase + pass * 64 + r) * VOCAB + nbase + c4) = v;
        }
        __syncthreads();
    }
}

// ---------------------------------------------------------------------------
// Launch
// Inputs: 0 tokens(int32) 1 emb 2 w_ih 3 w_hh 4 b_ih 5 b_hh 6 w_out 7 b_out
// ---------------------------------------------------------------------------
extern "C" void kernel_launch(void* const* d_in, const int* in_sizes, int n_in,
                              void* d_out, int out_size)
{
    const int*   tokens = (const int*)  d_in[0];
    const float* emb    = (const float*)d_in[1];
    const float* w_ih   = (const float*)d_in[2];
    const float* w_hh   = (const float*)d_in[3];
    const float* b_ih   = (const float*)d_in[4];
    const float* b_hh   = (const float*)d_in[5];
    const float* w_out  = (const float*)d_in[6];
    const float* b_out  = (const float*)d_in[7];
    float* out = (float*)d_out;

    (void)in_sizes; (void)n_in; (void)out_size;

    wconv_kernel<<<VOCAB * HID / 4 / 256, 256>>>(w_out);
    embed_xp_kernel<<<ROWS / 32, 192>>>(tokens, emb, w_ih, b_ih);
    gru_scan_kernel<<<BATCH, 128>>>(w_hh, b_hh);

    dim3 grid(VOCAB / GN, ROWS / GM);   // 250 x 32
    out_gemm_kernel<<<grid, 256>>>(b_out, out);
}